// round 1
// baseline (speedup 1.0000x reference)
#include <cuda_runtime.h>
#include <cuda_bf16.h>
#include <cstdint>

#define B_SZ 2
#define T_SZ 2048
#define C_SZ 2048
#define NH 16
#define NKV 4
#define HD 128
#define RMS_EPS 1.1920929e-07f
#define ATT_SCALE 0.08838834764831845f   // 1/sqrt(128)
#define NEG_BIG -1e30f

// ---------------- scratch (static device globals; no allocation) ----------------
__device__ float g_q[(size_t)B_SZ * T_SZ * NH * HD];    // [B*T, 2048]
__device__ float g_k[(size_t)B_SZ * T_SZ * NKV * HD];   // [B*T, 512]
__device__ float g_v[(size_t)B_SZ * T_SZ * NKV * HD];   // [B*T, 512]
__device__ float g_y[(size_t)B_SZ * T_SZ * C_SZ];       // [B*T, 2048]

// ---------------- generic SGEMM: C[M,N] = A[M,K] * B[N,K]^T (all row-major) ------
// 64x64 tile, K-chunk 16, 256 threads, 4x4 per thread.
__global__ __launch_bounds__(256) void sgemm_nt(const float* __restrict__ A,
                                                const float* __restrict__ B,
                                                float* __restrict__ C,
                                                int M, int N, int K) {
    __shared__ float As[16][68];
    __shared__ float Bs[16][68];
    const int tid = threadIdx.x;
    const int bm = blockIdx.y * 64;
    const int bn = blockIdx.x * 64;
    const int tx = tid & 15;
    const int ty = tid >> 4;
    const int lrow = tid >> 2;          // 0..63
    const int lk4  = (tid & 3) * 4;     // 0,4,8,12

    float acc[4][4];
#pragma unroll
    for (int i = 0; i < 4; i++)
#pragma unroll
        for (int j = 0; j < 4; j++) acc[i][j] = 0.f;

    const float* Aptr = A + (size_t)(bm + lrow) * K + lk4;
    const float* Bptr = B + (size_t)(bn + lrow) * K + lk4;

    for (int kk = 0; kk < K; kk += 16) {
        float4 av = *(const float4*)(Aptr + kk);
        float4 bv = *(const float4*)(Bptr + kk);
        As[lk4 + 0][lrow] = av.x; As[lk4 + 1][lrow] = av.y;
        As[lk4 + 2][lrow] = av.z; As[lk4 + 3][lrow] = av.w;
        Bs[lk4 + 0][lrow] = bv.x; Bs[lk4 + 1][lrow] = bv.y;
        Bs[lk4 + 2][lrow] = bv.z; Bs[lk4 + 3][lrow] = bv.w;
        __syncthreads();
#pragma unroll
        for (int k = 0; k < 16; k++) {
            float4 a = *(const float4*)&As[k][ty * 4];
            float4 b = *(const float4*)&Bs[k][tx * 4];
            acc[0][0] += a.x * b.x; acc[0][1] += a.x * b.y; acc[0][2] += a.x * b.z; acc[0][3] += a.x * b.w;
            acc[1][0] += a.y * b.x; acc[1][1] += a.y * b.y; acc[1][2] += a.y * b.z; acc[1][3] += a.y * b.w;
            acc[2][0] += a.z * b.x; acc[2][1] += a.z * b.y; acc[2][2] += a.z * b.z; acc[2][3] += a.z * b.w;
            acc[3][0] += a.w * b.x; acc[3][1] += a.w * b.y; acc[3][2] += a.w * b.z; acc[3][3] += a.w * b.w;
        }
        __syncthreads();
    }
#pragma unroll
    for (int i = 0; i < 4; i++) {
        float4 o;
        o.x = acc[i][0]; o.y = acc[i][1]; o.z = acc[i][2]; o.w = acc[i][3];
        *(float4*)(C + (size_t)(bm + ty * 4 + i) * N + bn + tx * 4) = o;
    }
}

// ---------------- RoPE + RMSNorm (in place on q or k buffer) --------------------
// one block = one (b, t, head) vector of 128; buf layout [(b*T+t)*n_head*128 + h*128 + d]
__global__ __launch_bounds__(128) void rope_rmsnorm(float* __restrict__ buf,
                                                    const float* __restrict__ cosb,
                                                    const float* __restrict__ sinb,
                                                    int n_head) {
    const int d = threadIdx.x;                 // 0..127
    const int vid = blockIdx.x;                // (b*T+t)*n_head + h
    const int t = (vid / n_head) % T_SZ;
    float* vec = buf + (size_t)vid * HD;

    float xv = vec[d];
    float xo = (d < HD / 2) ? -vec[d + HD / 2] : vec[d - HD / 2];
    float r = xv * cosb[t * HD + d] + xo * sinb[t * HD + d];

    // mean of squares over 128
    float s = r * r;
#pragma unroll
    for (int off = 16; off > 0; off >>= 1) s += __shfl_xor_sync(0xffffffffu, s, off);
    __shared__ float ws[4];
    const int lane = d & 31, wid = d >> 5;
    if (lane == 0) ws[wid] = s;
    __syncthreads();
    float tot = ws[0] + ws[1] + ws[2] + ws[3];
    float inv = rsqrtf(tot * (1.0f / HD) + RMS_EPS);
    vec[d] = r * inv;
}

// ---------------- flash attention (fp32, causal, GQA) ---------------------------
// CTA: (qtile, head, batch). BM=128 q rows, BN=64 key cols. 256 threads.
// tx = tid&7 (8 col-groups), ty = tid>>3 (32 row-groups of 4 rows).
// S microtile 4x8 (cols tx + 8j), O microtile 4x16 (cols tx*16..tx*16+15).
#define BM 128
#define BN 64
#define SQ_LD 132
#define SK_LD 132
#define SP_LD 68

__global__ __launch_bounds__(256, 1) void attn_kernel(const float* __restrict__ qb,
                                                      const float* __restrict__ kb,
                                                      const float* __restrict__ vb,
                                                      float* __restrict__ yb) {
    extern __shared__ float sm[];
    float* sQ = sm;                               // [128][132]
    float* sK = sQ + BM * SQ_LD;                  // [64][132]
    float* sV = sK + BN * SK_LD;                  // [64][132]
    float* sP = sV + BN * SK_LD;                  // [128][68]

    const int qt = blockIdx.x;
    const int h  = blockIdx.y;
    const int b  = blockIdx.z;
    const int kvh = h >> 2;
    const int qs = qt * BM;
    const int tid = threadIdx.x;
    const int tx = tid & 7;
    const int ty = tid >> 3;

    // load Q tile (reused for whole CTA)
    {
        const int r = tid >> 1;
        const int half = tid & 1;
        const float* src = qb + (size_t)(b * T_SZ + qs + r) * (NH * HD) + h * HD;
        float* dst = sQ + r * SQ_LD;
#pragma unroll
        for (int i = 0; i < 16; i++) {
            int d4 = half * 16 + i;
            *(float4*)(dst + d4 * 4) = *(const float4*)(src + d4 * 4);
        }
    }

    float mrow[4], lrow[4], o[4][16];
#pragma unroll
    for (int i = 0; i < 4; i++) {
        mrow[i] = NEG_BIG; lrow[i] = 0.f;
#pragma unroll
        for (int c = 0; c < 16; c++) o[i][c] = 0.f;
    }

    const int kend = qs + BM;   // causal: keys < qs+BM
    for (int ks = 0; ks < kend; ks += BN) {
        __syncthreads();
        // stage K, V tiles
        {
            const int r = tid >> 2;
            const int quad = tid & 3;
            const float* ksrc = kb + (size_t)(b * T_SZ + ks + r) * (NKV * HD) + kvh * HD;
            const float* vsrc = vb + (size_t)(b * T_SZ + ks + r) * (NKV * HD) + kvh * HD;
            float* kd = sK + r * SK_LD;
            float* vd = sV + r * SK_LD;
#pragma unroll
            for (int i = 0; i < 8; i++) {
                int d4 = quad * 8 + i;
                *(float4*)(kd + d4 * 4) = *(const float4*)(ksrc + d4 * 4);
                *(float4*)(vd + d4 * 4) = *(const float4*)(vsrc + d4 * 4);
            }
        }
        __syncthreads();

        // S = Q K^T
        float s[4][8];
#pragma unroll
        for (int i = 0; i < 4; i++)
#pragma unroll
            for (int j = 0; j < 8; j++) s[i][j] = 0.f;

#pragma unroll 4
        for (int d4 = 0; d4 < HD / 4; d4++) {
            float qf[4][4], kf[8][4];
#pragma unroll
            for (int i = 0; i < 4; i++) {
                float4 t = *(const float4*)(sQ + (ty * 4 + i) * SQ_LD + d4 * 4);
                qf[i][0] = t.x; qf[i][1] = t.y; qf[i][2] = t.z; qf[i][3] = t.w;
            }
#pragma unroll
            for (int j = 0; j < 8; j++) {
                float4 t = *(const float4*)(sK + (tx + 8 * j) * SK_LD + d4 * 4);
                kf[j][0] = t.x; kf[j][1] = t.y; kf[j][2] = t.z; kf[j][3] = t.w;
            }
#pragma unroll
            for (int i = 0; i < 4; i++)
#pragma unroll
                for (int j = 0; j < 8; j++)
#pragma unroll
                    for (int e = 0; e < 4; e++) s[i][j] += qf[i][e] * kf[j][e];
        }

        // online softmax
        const bool needs_mask = (ks + BN - 1) > qs;
#pragma unroll
        for (int i = 0; i < 4; i++) {
            const int qi = qs + ty * 4 + i;
            float rm = NEG_BIG;
#pragma unroll
            for (int j = 0; j < 8; j++) {
                float sv = s[i][j] * ATT_SCALE;
                if (needs_mask && (ks + tx + 8 * j) > qi) sv = NEG_BIG;
                s[i][j] = sv;
                rm = fmaxf(rm, sv);
            }
            rm = fmaxf(rm, __shfl_xor_sync(0xffffffffu, rm, 1));
            rm = fmaxf(rm, __shfl_xor_sync(0xffffffffu, rm, 2));
            rm = fmaxf(rm, __shfl_xor_sync(0xffffffffu, rm, 4));

            float mn = fmaxf(mrow[i], rm);
            float corr = __expf(mrow[i] - mn);
            float rs = 0.f;
#pragma unroll
            for (int j = 0; j < 8; j++) {
                float p = __expf(s[i][j] - mn);
                s[i][j] = p;
                rs += p;
            }
            rs += __shfl_xor_sync(0xffffffffu, rs, 1);
            rs += __shfl_xor_sync(0xffffffffu, rs, 2);
            rs += __shfl_xor_sync(0xffffffffu, rs, 4);

            lrow[i] = lrow[i] * corr + rs;
            mrow[i] = mn;
#pragma unroll
            for (int c = 0; c < 16; c++) o[i][c] *= corr;
        }

        // write P to shared for the PV gemm
#pragma unroll
        for (int i = 0; i < 4; i++)
#pragma unroll
            for (int j = 0; j < 8; j++)
                sP[(ty * 4 + i) * SP_LD + tx + 8 * j] = s[i][j];
        __syncthreads();

        // O += P V
#pragma unroll 2
        for (int j4 = 0; j4 < BN / 4; j4++) {
            float pr[4][4];
#pragma unroll
            for (int i = 0; i < 4; i++) {
                float4 t = *(const float4*)(sP + (ty * 4 + i) * SP_LD + j4 * 4);
                pr[i][0] = t.x; pr[i][1] = t.y; pr[i][2] = t.z; pr[i][3] = t.w;
            }
#pragma unroll
            for (int jj = 0; jj < 4; jj++) {
                const int kr = j4 * 4 + jj;
                float vv[16];
#pragma unroll
                for (int q4 = 0; q4 < 4; q4++) {
                    float4 t = *(const float4*)(sV + kr * SK_LD + tx * 16 + q4 * 4);
                    vv[q4 * 4 + 0] = t.x; vv[q4 * 4 + 1] = t.y;
                    vv[q4 * 4 + 2] = t.z; vv[q4 * 4 + 3] = t.w;
                }
#pragma unroll
                for (int i = 0; i < 4; i++)
#pragma unroll
                    for (int c = 0; c < 16; c++) o[i][c] += pr[i][jj] * vv[c];
            }
        }
        // next iteration's __syncthreads() (top of loop) protects sK/sV/sP reuse
    }

    // epilogue: normalize and store
#pragma unroll
    for (int i = 0; i < 4; i++) {
        const float inv = 1.0f / lrow[i];
        const int r = ty * 4 + i;
        float* dst = yb + (size_t)(b * T_SZ + qs + r) * C_SZ + h * HD + tx * 16;
#pragma unroll
        for (int c4 = 0; c4 < 4; c4++) {
            float4 t;
            t.x = o[i][c4 * 4 + 0] * inv;
            t.y = o[i][c4 * 4 + 1] * inv;
            t.z = o[i][c4 * 4 + 2] * inv;
            t.w = o[i][c4 * 4 + 3] * inv;
            *(float4*)(dst + c4 * 4) = t;
        }
    }
}

// ---------------- launch ---------------------------------------------------------
extern "C" void kernel_launch(void* const* d_in, const int* in_sizes, int n_in,
                              void* d_out, int out_size) {
    const float* x     = (const float*)d_in[0];
    const float* cosb  = (const float*)d_in[1];
    const float* sinb  = (const float*)d_in[2];
    const float* wq    = (const float*)d_in[3];
    const float* wk    = (const float*)d_in[4];
    const float* wv    = (const float*)d_in[5];
    const float* wproj = (const float*)d_in[6];
    float* out = (float*)d_out;

    float *qp, *kp, *vp, *yp;
    cudaGetSymbolAddress((void**)&qp, g_q);
    cudaGetSymbolAddress((void**)&kp, g_k);
    cudaGetSymbolAddress((void**)&vp, g_v);
    cudaGetSymbolAddress((void**)&yp, g_y);

    const int M = B_SZ * T_SZ;   // 4096

    // QKV projections
    sgemm_nt<<<dim3(C_SZ / 64, M / 64), 256>>>(x, wq, qp, M, NH * HD, C_SZ);
    sgemm_nt<<<dim3((NKV * HD) / 64, M / 64), 256>>>(x, wk, kp, M, NKV * HD, C_SZ);
    sgemm_nt<<<dim3((NKV * HD) / 64, M / 64), 256>>>(x, wv, vp, M, NKV * HD, C_SZ);

    // RoPE + RMSNorm on q and k
    rope_rmsnorm<<<M * NH, 128>>>(qp, cosb, sinb, NH);
    rope_rmsnorm<<<M * NKV, 128>>>(kp, cosb, sinb, NKV);

    // attention
    const int smem = (BM * SQ_LD + 2 * BN * SK_LD + BM * SP_LD) * sizeof(float); // ~170KB
    cudaFuncSetAttribute(attn_kernel, cudaFuncAttributeMaxDynamicSharedMemorySize, smem);
    attn_kernel<<<dim3(T_SZ / BM, NH, B_SZ), 256, smem>>>(qp, kp, vp, yp);

    // output projection
    sgemm_nt<<<dim3(C_SZ / 64, M / 64), 256>>>(yp, wproj, out, M, C_SZ, C_SZ);
}

// round 2
// speedup vs baseline: 1.6554x; 1.6554x over previous
#include <cuda_runtime.h>
#include <cuda_bf16.h>
#include <cstdint>

#define B_SZ 2
#define T_SZ 2048
#define C_SZ 2048
#define NH 16
#define NKV 4
#define HD 128
#define RMS_EPS 1.1920929e-07f
#define ATT_SCALE 0.08838834764831845f   // 1/sqrt(128)
#define NEG_BIG -1e30f

// ---------------- scratch (static device globals; no allocation) ----------------
__device__ float g_q[(size_t)B_SZ * T_SZ * NH * HD];    // [B*T, 2048]
__device__ float g_k[(size_t)B_SZ * T_SZ * NKV * HD];   // [B*T, 512]
__device__ float g_v[(size_t)B_SZ * T_SZ * NKV * HD];   // [B*T, 512]
__device__ float g_y[(size_t)B_SZ * T_SZ * C_SZ];       // [B*T, 2048]

// ---------------- TF32 tensor-core GEMM: C[M,N] = A[M,K] * B[N,K]^T ---------------
// 128x128 CTA tile, K-chunk 32, 256 threads (8 warps, 2x4), warp tile 64x32.
// mma.sync.aligned.m16n8k8 tf32. Register-prefetch pipeline; cvt.rna at STS.

__device__ __forceinline__ uint32_t f2tf(float f) {
    uint32_t u;
    asm("cvt.rna.tf32.f32 %0, %1;" : "=r"(u) : "f"(f));
    return u;
}

__device__ __forceinline__ void mma_tf32(float* c, const uint32_t* a, const uint32_t* b) {
    asm volatile("mma.sync.aligned.m16n8k8.row.col.f32.tf32.tf32.f32 "
                 "{%0,%1,%2,%3}, {%4,%5,%6,%7}, {%8,%9}, {%0,%1,%2,%3};"
                 : "+f"(c[0]), "+f"(c[1]), "+f"(c[2]), "+f"(c[3])
                 : "r"(a[0]), "r"(a[1]), "r"(a[2]), "r"(a[3]),
                   "r"(b[0]), "r"(b[1]));
}

__global__ __launch_bounds__(256, 1) void gemm_tf32(const float* __restrict__ A,
                                                    const float* __restrict__ B,
                                                    float* __restrict__ C,
                                                    int M, int N, int K) {
    __shared__ uint32_t As[128][36];
    __shared__ uint32_t Bs[128][36];

    const int tid  = threadIdx.x;
    const int bm   = blockIdx.y * 128;
    const int bn   = blockIdx.x * 128;
    const int warp = tid >> 5;
    const int lane = tid & 31;
    const int wm   = warp >> 2;          // 0..1
    const int wn   = warp & 3;           // 0..3
    const int g    = lane >> 2;          // 0..7
    const int t    = lane & 3;           // 0..3
    const int arow = tid >> 3;           // 0..31
    const int ac4  = (tid & 7) * 4;      // 0,4,...,28

    float acc[4][4][4];
#pragma unroll
    for (int mi = 0; mi < 4; mi++)
#pragma unroll
        for (int ni = 0; ni < 4; ni++)
#pragma unroll
            for (int r = 0; r < 4; r++) acc[mi][ni][r] = 0.f;

    const float* Ag = A + (size_t)(bm + arow) * K + ac4;
    const float* Bg = B + (size_t)(bn + arow) * K + ac4;

    float4 ra[4], rb[4];
#pragma unroll
    for (int p = 0; p < 4; p++) {
        ra[p] = *(const float4*)(Ag + (size_t)p * 32 * K);
        rb[p] = *(const float4*)(Bg + (size_t)p * 32 * K);
    }

    for (int kk = 0; kk < K; kk += 32) {
        // convert + store staged tile
#pragma unroll
        for (int p = 0; p < 4; p++) {
            As[arow + 32 * p][ac4 + 0] = f2tf(ra[p].x);
            As[arow + 32 * p][ac4 + 1] = f2tf(ra[p].y);
            As[arow + 32 * p][ac4 + 2] = f2tf(ra[p].z);
            As[arow + 32 * p][ac4 + 3] = f2tf(ra[p].w);
            Bs[arow + 32 * p][ac4 + 0] = f2tf(rb[p].x);
            Bs[arow + 32 * p][ac4 + 1] = f2tf(rb[p].y);
            Bs[arow + 32 * p][ac4 + 2] = f2tf(rb[p].z);
            Bs[arow + 32 * p][ac4 + 3] = f2tf(rb[p].w);
        }
        __syncthreads();

        // prefetch next K-chunk while computing this one
        if (kk + 32 < K) {
#pragma unroll
            for (int p = 0; p < 4; p++) {
                ra[p] = *(const float4*)(Ag + (size_t)p * 32 * K + kk + 32);
                rb[p] = *(const float4*)(Bg + (size_t)p * 32 * K + kk + 32);
            }
        }

#pragma unroll
        for (int k8 = 0; k8 < 4; k8++) {
            const int kc = k8 * 8;
            uint32_t af[4][4], bf[4][2];
#pragma unroll
            for (int mi = 0; mi < 4; mi++) {
                const int r = wm * 64 + mi * 16 + g;
                af[mi][0] = As[r][kc + t];
                af[mi][1] = As[r + 8][kc + t];
                af[mi][2] = As[r][kc + t + 4];
                af[mi][3] = As[r + 8][kc + t + 4];
            }
#pragma unroll
            for (int ni = 0; ni < 4; ni++) {
                const int c = wn * 32 + ni * 8 + g;
                bf[ni][0] = Bs[c][kc + t];
                bf[ni][1] = Bs[c][kc + t + 4];
            }
#pragma unroll
            for (int mi = 0; mi < 4; mi++)
#pragma unroll
                for (int ni = 0; ni < 4; ni++)
                    mma_tf32(acc[mi][ni], af[mi], bf[ni]);
        }
        __syncthreads();
    }

    // epilogue
#pragma unroll
    for (int mi = 0; mi < 4; mi++) {
        const int r = bm + wm * 64 + mi * 16 + g;
#pragma unroll
        for (int ni = 0; ni < 4; ni++) {
            const int c = bn + wn * 32 + ni * 8 + 2 * t;
            *(float2*)&C[(size_t)r * N + c] = make_float2(acc[mi][ni][0], acc[mi][ni][1]);
            *(float2*)&C[(size_t)(r + 8) * N + c] = make_float2(acc[mi][ni][2], acc[mi][ni][3]);
        }
    }
}

// ---------------- RoPE + RMSNorm (in place on q or k buffer) --------------------
__global__ __launch_bounds__(128) void rope_rmsnorm(float* __restrict__ buf,
                                                    const float* __restrict__ cosb,
                                                    const float* __restrict__ sinb,
                                                    int n_head) {
    const int d = threadIdx.x;                 // 0..127
    const int vid = blockIdx.x;                // (b*T+t)*n_head + h
    const int t = (vid / n_head) % T_SZ;
    float* vec = buf + (size_t)vid * HD;

    float xv = vec[d];
    float xo = (d < HD / 2) ? -vec[d + HD / 2] : vec[d - HD / 2];
    float r = xv * cosb[t * HD + d] + xo * sinb[t * HD + d];

    float s = r * r;
#pragma unroll
    for (int off = 16; off > 0; off >>= 1) s += __shfl_xor_sync(0xffffffffu, s, off);
    __shared__ float ws[4];
    const int lane = d & 31, wid = d >> 5;
    if (lane == 0) ws[wid] = s;
    __syncthreads();
    float tot = ws[0] + ws[1] + ws[2] + ws[3];
    float inv = rsqrtf(tot * (1.0f / HD) + RMS_EPS);
    vec[d] = r * inv;
}

// ---------------- flash attention (fp32, causal, GQA) ---------------------------
#define BM 128
#define BN 64
#define SQ_LD 132
#define SK_LD 132
#define SP_LD 68

__global__ __launch_bounds__(256, 1) void attn_kernel(const float* __restrict__ qb,
                                                      const float* __restrict__ kb,
                                                      const float* __restrict__ vb,
                                                      float* __restrict__ yb) {
    extern __shared__ float sm[];
    float* sQ = sm;                               // [128][132]
    float* sK = sQ + BM * SQ_LD;                  // [64][132]
    float* sV = sK + BN * SK_LD;                  // [64][132]
    float* sP = sV + BN * SK_LD;                  // [128][68]

    const int qt = blockIdx.x;
    const int h  = blockIdx.y;
    const int b  = blockIdx.z;
    const int kvh = h >> 2;
    const int qs = qt * BM;
    const int tid = threadIdx.x;
    const int tx = tid & 7;
    const int ty = tid >> 3;

    {
        const int r = tid >> 1;
        const int half = tid & 1;
        const float* src = qb + (size_t)(b * T_SZ + qs + r) * (NH * HD) + h * HD;
        float* dst = sQ + r * SQ_LD;
#pragma unroll
        for (int i = 0; i < 16; i++) {
            int d4 = half * 16 + i;
            *(float4*)(dst + d4 * 4) = *(const float4*)(src + d4 * 4);
        }
    }

    float mrow[4], lrow[4], o[4][16];
#pragma unroll
    for (int i = 0; i < 4; i++) {
        mrow[i] = NEG_BIG; lrow[i] = 0.f;
#pragma unroll
        for (int c = 0; c < 16; c++) o[i][c] = 0.f;
    }

    const int kend = qs + BM;
    for (int ks = 0; ks < kend; ks += BN) {
        __syncthreads();
        {
            const int r = tid >> 2;
            const int quad = tid & 3;
            const float* ksrc = kb + (size_t)(b * T_SZ + ks + r) * (NKV * HD) + kvh * HD;
            const float* vsrc = vb + (size_t)(b * T_SZ + ks + r) * (NKV * HD) + kvh * HD;
            float* kd = sK + r * SK_LD;
            float* vd = sV + r * SK_LD;
#pragma unroll
            for (int i = 0; i < 8; i++) {
                int d4 = quad * 8 + i;
                *(float4*)(kd + d4 * 4) = *(const float4*)(ksrc + d4 * 4);
                *(float4*)(vd + d4 * 4) = *(const float4*)(vsrc + d4 * 4);
            }
        }
        __syncthreads();

        float s[4][8];
#pragma unroll
        for (int i = 0; i < 4; i++)
#pragma unroll
            for (int j = 0; j < 8; j++) s[i][j] = 0.f;

#pragma unroll 4
        for (int d4 = 0; d4 < HD / 4; d4++) {
            float qf[4][4], kf[8][4];
#pragma unroll
            for (int i = 0; i < 4; i++) {
                float4 t = *(const float4*)(sQ + (ty * 4 + i) * SQ_LD + d4 * 4);
                qf[i][0] = t.x; qf[i][1] = t.y; qf[i][2] = t.z; qf[i][3] = t.w;
            }
#pragma unroll
            for (int j = 0; j < 8; j++) {
                float4 t = *(const float4*)(sK + (tx + 8 * j) * SK_LD + d4 * 4);
                kf[j][0] = t.x; kf[j][1] = t.y; kf[j][2] = t.z; kf[j][3] = t.w;
            }
#pragma unroll
            for (int i = 0; i < 4; i++)
#pragma unroll
                for (int j = 0; j < 8; j++)
#pragma unroll
                    for (int e = 0; e < 4; e++) s[i][j] += qf[i][e] * kf[j][e];
        }

        const bool needs_mask = (ks + BN - 1) > qs;
#pragma unroll
        for (int i = 0; i < 4; i++) {
            const int qi = qs + ty * 4 + i;
            float rm = NEG_BIG;
#pragma unroll
            for (int j = 0; j < 8; j++) {
                float sv = s[i][j] * ATT_SCALE;
                if (needs_mask && (ks + tx + 8 * j) > qi) sv = NEG_BIG;
                s[i][j] = sv;
                rm = fmaxf(rm, sv);
            }
            rm = fmaxf(rm, __shfl_xor_sync(0xffffffffu, rm, 1));
            rm = fmaxf(rm, __shfl_xor_sync(0xffffffffu, rm, 2));
            rm = fmaxf(rm, __shfl_xor_sync(0xffffffffu, rm, 4));

            float mn = fmaxf(mrow[i], rm);
            float corr = __expf(mrow[i] - mn);
            float rs = 0.f;
#pragma unroll
            for (int j = 0; j < 8; j++) {
                float p = __expf(s[i][j] - mn);
                s[i][j] = p;
                rs += p;
            }
            rs += __shfl_xor_sync(0xffffffffu, rs, 1);
            rs += __shfl_xor_sync(0xffffffffu, rs, 2);
            rs += __shfl_xor_sync(0xffffffffu, rs, 4);

            lrow[i] = lrow[i] * corr + rs;
            mrow[i] = mn;
#pragma unroll
            for (int c = 0; c < 16; c++) o[i][c] *= corr;
        }

#pragma unroll
        for (int i = 0; i < 4; i++)
#pragma unroll
            for (int j = 0; j < 8; j++)
                sP[(ty * 4 + i) * SP_LD + tx + 8 * j] = s[i][j];
        __syncthreads();

#pragma unroll 2
        for (int j4 = 0; j4 < BN / 4; j4++) {
            float pr[4][4];
#pragma unroll
            for (int i = 0; i < 4; i++) {
                float4 t = *(const float4*)(sP + (ty * 4 + i) * SP_LD + j4 * 4);
                pr[i][0] = t.x; pr[i][1] = t.y; pr[i][2] = t.z; pr[i][3] = t.w;
            }
#pragma unroll
            for (int jj = 0; jj < 4; jj++) {
                const int kr = j4 * 4 + jj;
                float vv[16];
#pragma unroll
                for (int q4 = 0; q4 < 4; q4++) {
                    float4 t = *(const float4*)(sV + kr * SK_LD + tx * 16 + q4 * 4);
                    vv[q4 * 4 + 0] = t.x; vv[q4 * 4 + 1] = t.y;
                    vv[q4 * 4 + 2] = t.z; vv[q4 * 4 + 3] = t.w;
                }
#pragma unroll
                for (int i = 0; i < 4; i++)
#pragma unroll
                    for (int c = 0; c < 16; c++) o[i][c] += pr[i][jj] * vv[c];
            }
        }
    }

#pragma unroll
    for (int i = 0; i < 4; i++) {
        const float inv = 1.0f / lrow[i];
        const int r = ty * 4 + i;
        float* dst = yb + (size_t)(b * T_SZ + qs + r) * C_SZ + h * HD + tx * 16;
#pragma unroll
        for (int c4 = 0; c4 < 4; c4++) {
            float4 t;
            t.x = o[i][c4 * 4 + 0] * inv;
            t.y = o[i][c4 * 4 + 1] * inv;
            t.z = o[i][c4 * 4 + 2] * inv;
            t.w = o[i][c4 * 4 + 3] * inv;
            *(float4*)(dst + c4 * 4) = t;
        }
    }
}

// ---------------- launch ---------------------------------------------------------
extern "C" void kernel_launch(void* const* d_in, const int* in_sizes, int n_in,
                              void* d_out, int out_size) {
    const float* x     = (const float*)d_in[0];
    const float* cosb  = (const float*)d_in[1];
    const float* sinb  = (const float*)d_in[2];
    const float* wq    = (const float*)d_in[3];
    const float* wk    = (const float*)d_in[4];
    const float* wv    = (const float*)d_in[5];
    const float* wproj = (const float*)d_in[6];
    float* out = (float*)d_out;

    float *qp, *kp, *vp, *yp;
    cudaGetSymbolAddress((void**)&qp, g_q);
    cudaGetSymbolAddress((void**)&kp, g_k);
    cudaGetSymbolAddress((void**)&vp, g_v);
    cudaGetSymbolAddress((void**)&yp, g_y);

    const int M = B_SZ * T_SZ;   // 4096

    // QKV projections (TF32 tensor cores)
    gemm_tf32<<<dim3((NH * HD) / 128, M / 128), 256>>>(x, wq, qp, M, NH * HD, C_SZ);
    gemm_tf32<<<dim3((NKV * HD) / 128, M / 128), 256>>>(x, wk, kp, M, NKV * HD, C_SZ);
    gemm_tf32<<<dim3((NKV * HD) / 128, M / 128), 256>>>(x, wv, vp, M, NKV * HD, C_SZ);

    // RoPE + RMSNorm on q and k
    rope_rmsnorm<<<M * NH, 128>>>(qp, cosb, sinb, NH);
    rope_rmsnorm<<<M * NKV, 128>>>(kp, cosb, sinb, NKV);

    // attention (fp32 for now)
    const int smem = (BM * SQ_LD + 2 * BN * SK_LD + BM * SP_LD) * sizeof(float); // ~170KB
    cudaFuncSetAttribute(attn_kernel, cudaFuncAttributeMaxDynamicSharedMemorySize, smem);
    attn_kernel<<<dim3(T_SZ / BM, NH, B_SZ), 256, smem>>>(qp, kp, vp, yp);

    // output projection (TF32 tensor cores)
    gemm_tf32<<<dim3(C_SZ / 128, M / 128), 256>>>(yp, wproj, out, M, C_SZ, C_SZ);
}

// round 3
// speedup vs baseline: 3.4430x; 2.0798x over previous
#include <cuda_runtime.h>
#include <cuda_bf16.h>
#include <cstdint>

#define B_SZ 2
#define T_SZ 2048
#define C_SZ 2048
#define NH 16
#define NKV 4
#define HD 128
#define RMS_EPS 1.1920929e-07f
#define ATT_SCALE 0.08838834764831845f   // 1/sqrt(128)
#define NEG_BIG -1e30f

// ---------------- scratch (static device globals; no allocation) ----------------
__device__ float g_q[(size_t)B_SZ * T_SZ * NH * HD];    // [B*T, 2048]
__device__ float g_k[(size_t)B_SZ * T_SZ * NKV * HD];   // [B*T, 512]
__device__ float g_v[(size_t)B_SZ * T_SZ * NKV * HD];   // [B*T, 512]
__device__ float g_y[(size_t)B_SZ * T_SZ * C_SZ];       // [B*T, 2048]

// ---------------- TF32 helpers ---------------------------------------------------
__device__ __forceinline__ uint32_t f2tf(float f) {
    uint32_t u;
    asm("cvt.rna.tf32.f32 %0, %1;" : "=r"(u) : "f"(f));
    return u;
}

__device__ __forceinline__ void mma_tf32(float* c, const uint32_t* a, const uint32_t* b) {
    asm volatile("mma.sync.aligned.m16n8k8.row.col.f32.tf32.tf32.f32 "
                 "{%0,%1,%2,%3}, {%4,%5,%6,%7}, {%8,%9}, {%0,%1,%2,%3};"
                 : "+f"(c[0]), "+f"(c[1]), "+f"(c[2]), "+f"(c[3])
                 : "r"(a[0]), "r"(a[1]), "r"(a[2]), "r"(a[3]),
                   "r"(b[0]), "r"(b[1]));
}

// ---------------- TF32 tensor-core GEMM: C[M,N] = A[M,K] * B[N,K]^T ---------------
__global__ __launch_bounds__(256, 1) void gemm_tf32(const float* __restrict__ A,
                                                    const float* __restrict__ B,
                                                    float* __restrict__ C,
                                                    int M, int N, int K) {
    __shared__ uint32_t As[128][36];
    __shared__ uint32_t Bs[128][36];

    const int tid  = threadIdx.x;
    const int bm   = blockIdx.y * 128;
    const int bn   = blockIdx.x * 128;
    const int warp = tid >> 5;
    const int lane = tid & 31;
    const int wm   = warp >> 2;          // 0..1
    const int wn   = warp & 3;           // 0..3
    const int g    = lane >> 2;          // 0..7
    const int t    = lane & 3;           // 0..3
    const int arow = tid >> 3;           // 0..31
    const int ac4  = (tid & 7) * 4;      // 0,4,...,28

    float acc[4][4][4];
#pragma unroll
    for (int mi = 0; mi < 4; mi++)
#pragma unroll
        for (int ni = 0; ni < 4; ni++)
#pragma unroll
            for (int r = 0; r < 4; r++) acc[mi][ni][r] = 0.f;

    const float* Ag = A + (size_t)(bm + arow) * K + ac4;
    const float* Bg = B + (size_t)(bn + arow) * K + ac4;

    float4 ra[4], rb[4];
#pragma unroll
    for (int p = 0; p < 4; p++) {
        ra[p] = *(const float4*)(Ag + (size_t)p * 32 * K);
        rb[p] = *(const float4*)(Bg + (size_t)p * 32 * K);
    }

    for (int kk = 0; kk < K; kk += 32) {
#pragma unroll
        for (int p = 0; p < 4; p++) {
            As[arow + 32 * p][ac4 + 0] = f2tf(ra[p].x);
            As[arow + 32 * p][ac4 + 1] = f2tf(ra[p].y);
            As[arow + 32 * p][ac4 + 2] = f2tf(ra[p].z);
            As[arow + 32 * p][ac4 + 3] = f2tf(ra[p].w);
            Bs[arow + 32 * p][ac4 + 0] = f2tf(rb[p].x);
            Bs[arow + 32 * p][ac4 + 1] = f2tf(rb[p].y);
            Bs[arow + 32 * p][ac4 + 2] = f2tf(rb[p].z);
            Bs[arow + 32 * p][ac4 + 3] = f2tf(rb[p].w);
        }
        __syncthreads();

        if (kk + 32 < K) {
#pragma unroll
            for (int p = 0; p < 4; p++) {
                ra[p] = *(const float4*)(Ag + (size_t)p * 32 * K + kk + 32);
                rb[p] = *(const float4*)(Bg + (size_t)p * 32 * K + kk + 32);
            }
        }

#pragma unroll
        for (int k8 = 0; k8 < 4; k8++) {
            const int kc = k8 * 8;
            uint32_t af[4][4], bf[4][2];
#pragma unroll
            for (int mi = 0; mi < 4; mi++) {
                const int r = wm * 64 + mi * 16 + g;
                af[mi][0] = As[r][kc + t];
                af[mi][1] = As[r + 8][kc + t];
                af[mi][2] = As[r][kc + t + 4];
                af[mi][3] = As[r + 8][kc + t + 4];
            }
#pragma unroll
            for (int ni = 0; ni < 4; ni++) {
                const int c = wn * 32 + ni * 8 + g;
                bf[ni][0] = Bs[c][kc + t];
                bf[ni][1] = Bs[c][kc + t + 4];
            }
#pragma unroll
            for (int mi = 0; mi < 4; mi++)
#pragma unroll
                for (int ni = 0; ni < 4; ni++)
                    mma_tf32(acc[mi][ni], af[mi], bf[ni]);
        }
        __syncthreads();
    }

#pragma unroll
    for (int mi = 0; mi < 4; mi++) {
        const int r = bm + wm * 64 + mi * 16 + g;
#pragma unroll
        for (int ni = 0; ni < 4; ni++) {
            const int c = bn + wn * 32 + ni * 8 + 2 * t;
            *(float2*)&C[(size_t)r * N + c] = make_float2(acc[mi][ni][0], acc[mi][ni][1]);
            *(float2*)&C[(size_t)(r + 8) * N + c] = make_float2(acc[mi][ni][2], acc[mi][ni][3]);
        }
    }
}

// ---------------- RoPE + RMSNorm (in place on q or k buffer) --------------------
__global__ __launch_bounds__(128) void rope_rmsnorm(float* __restrict__ buf,
                                                    const float* __restrict__ cosb,
                                                    const float* __restrict__ sinb,
                                                    int n_head) {
    const int d = threadIdx.x;                 // 0..127
    const int vid = blockIdx.x;                // (b*T+t)*n_head + h
    const int t = (vid / n_head) % T_SZ;
    float* vec = buf + (size_t)vid * HD;

    float xv = vec[d];
    float xo = (d < HD / 2) ? -vec[d + HD / 2] : vec[d - HD / 2];
    float r = xv * cosb[t * HD + d] + xo * sinb[t * HD + d];

    float s = r * r;
#pragma unroll
    for (int off = 16; off > 0; off >>= 1) s += __shfl_xor_sync(0xffffffffu, s, off);
    __shared__ float ws[4];
    const int lane = d & 31, wid = d >> 5;
    if (lane == 0) ws[wid] = s;
    __syncthreads();
    float tot = ws[0] + ws[1] + ws[2] + ws[3];
    float inv = rsqrtf(tot * (1.0f / HD) + RMS_EPS);
    vec[d] = r * inv;
}

// ---------------- flash attention (TF32 tensor cores, causal, GQA) ---------------
// BM=128 q rows, BN=64 keys, 8 warps; warp w owns q rows [w*16, w*16+16).
// Q held in registers as mma A-fragments for the whole CTA lifetime.
#define BM 128
#define BN 64
#define SK_LD 132   // banks (4g+t): conflict-free for S B-frag loads
#define SV_LD 136   // banks (8t+g): conflict-free for PV B-frag loads
#define SP_LD 68

__global__ __launch_bounds__(256, 1) void attn_tc(const float* __restrict__ qb,
                                                  const float* __restrict__ kb,
                                                  const float* __restrict__ vb,
                                                  float* __restrict__ yb) {
    extern __shared__ uint32_t smu[];
    uint32_t* sK = smu;                       // [64][132]
    uint32_t* sV = sK + BN * SK_LD;           // [64][136]
    uint32_t* sP = sV + BN * SV_LD;           // [128][68]

    const int qt = blockIdx.x;
    const int h  = blockIdx.y;
    const int b  = blockIdx.z;
    const int kvh = h >> 2;
    const int qs = qt * BM;
    const int tid  = threadIdx.x;
    const int w    = tid >> 5;
    const int lane = tid & 31;
    const int g    = lane >> 2;
    const int t    = lane & 3;
    const int w16  = w * 16;

    // ---- load Q fragments into registers (tf32) ----
    uint32_t qa[16][4];
    {
        const float* q0 = qb + (size_t)(b * T_SZ + qs + w16 + g) * (NH * HD) + h * HD;
        const float* q1 = q0 + (size_t)8 * (NH * HD);
#pragma unroll
        for (int kc = 0; kc < 16; kc++) {
            qa[kc][0] = f2tf(q0[kc * 8 + t]);
            qa[kc][1] = f2tf(q1[kc * 8 + t]);
            qa[kc][2] = f2tf(q0[kc * 8 + t + 4]);
            qa[kc][3] = f2tf(q1[kc * 8 + t + 4]);
        }
    }

    float m0 = NEG_BIG, m1 = NEG_BIG, l0 = 0.f, l1 = 0.f;
    float o[16][4];
#pragma unroll
    for (int dt = 0; dt < 16; dt++)
#pragma unroll
        for (int r = 0; r < 4; r++) o[dt][r] = 0.f;

    const int row0 = qs + w16 + g;
    const int row1 = row0 + 8;

    const int kend = qs + BM;
    for (int ks = 0; ks < kend; ks += BN) {
        __syncthreads();   // protect sK/sV against previous iteration's readers
        // ---- stage K,V tiles (fp32 -> tf32) ----
        {
            const int r = tid >> 2;          // 0..63
            const int quad = tid & 3;
            const float* ksrc = kb + (size_t)(b * T_SZ + ks + r) * (NKV * HD) + kvh * HD;
            const float* vsrc = vb + (size_t)(b * T_SZ + ks + r) * (NKV * HD) + kvh * HD;
#pragma unroll
            for (int i = 0; i < 8; i++) {
                const int d4 = quad * 8 + i;
                float4 kf = *(const float4*)(ksrc + d4 * 4);
                float4 vf = *(const float4*)(vsrc + d4 * 4);
                uint4 kt4 = make_uint4(f2tf(kf.x), f2tf(kf.y), f2tf(kf.z), f2tf(kf.w));
                uint4 vt4 = make_uint4(f2tf(vf.x), f2tf(vf.y), f2tf(vf.z), f2tf(vf.w));
                *(uint4*)&sK[r * SK_LD + d4 * 4] = kt4;
                *(uint4*)&sV[r * SV_LD + d4 * 4] = vt4;
            }
        }
        __syncthreads();

        // ---- S = Q K^T (16 x 64 per warp) ----
        float s[8][4];
#pragma unroll
        for (int nt = 0; nt < 8; nt++)
#pragma unroll
            for (int r = 0; r < 4; r++) s[nt][r] = 0.f;

#pragma unroll
        for (int kc = 0; kc < 16; kc++) {
#pragma unroll
            for (int nt = 0; nt < 8; nt++) {
                uint32_t bf[2];
                bf[0] = sK[(nt * 8 + g) * SK_LD + kc * 8 + t];
                bf[1] = sK[(nt * 8 + g) * SK_LD + kc * 8 + t + 4];
                mma_tf32(s[nt], qa[kc], bf);
            }
        }

        // ---- online softmax on accumulator fragments ----
        const bool needs_mask = (ks + BN - 1) > (qs + w16);
        float rm0 = NEG_BIG, rm1 = NEG_BIG;
#pragma unroll
        for (int nt = 0; nt < 8; nt++) {
#pragma unroll
            for (int ci = 0; ci < 2; ci++) {
                const int col = ks + nt * 8 + 2 * t + ci;
                float v0 = s[nt][ci] * ATT_SCALE;
                float v1 = s[nt][2 + ci] * ATT_SCALE;
                if (needs_mask) {
                    if (col > row0) v0 = NEG_BIG;
                    if (col > row1) v1 = NEG_BIG;
                }
                s[nt][ci] = v0;
                s[nt][2 + ci] = v1;
                rm0 = fmaxf(rm0, v0);
                rm1 = fmaxf(rm1, v1);
            }
        }
        rm0 = fmaxf(rm0, __shfl_xor_sync(0xffffffffu, rm0, 1));
        rm0 = fmaxf(rm0, __shfl_xor_sync(0xffffffffu, rm0, 2));
        rm1 = fmaxf(rm1, __shfl_xor_sync(0xffffffffu, rm1, 1));
        rm1 = fmaxf(rm1, __shfl_xor_sync(0xffffffffu, rm1, 2));

        const float mn0 = fmaxf(m0, rm0);
        const float mn1 = fmaxf(m1, rm1);
        const float corr0 = __expf(m0 - mn0);
        const float corr1 = __expf(m1 - mn1);
        m0 = mn0; m1 = mn1;

        float rs0 = 0.f, rs1 = 0.f;
#pragma unroll
        for (int nt = 0; nt < 8; nt++) {
#pragma unroll
            for (int ci = 0; ci < 2; ci++) {
                float p0 = __expf(s[nt][ci] - mn0);
                float p1 = __expf(s[nt][2 + ci] - mn1);
                s[nt][ci] = p0;
                s[nt][2 + ci] = p1;
                rs0 += p0;
                rs1 += p1;
            }
        }
        rs0 += __shfl_xor_sync(0xffffffffu, rs0, 1);
        rs0 += __shfl_xor_sync(0xffffffffu, rs0, 2);
        rs1 += __shfl_xor_sync(0xffffffffu, rs1, 1);
        rs1 += __shfl_xor_sync(0xffffffffu, rs1, 2);

        l0 = l0 * corr0 + rs0;
        l1 = l1 * corr1 + rs1;

#pragma unroll
        for (int dt = 0; dt < 16; dt++) {
            o[dt][0] *= corr0; o[dt][1] *= corr0;
            o[dt][2] *= corr1; o[dt][3] *= corr1;
        }

        // ---- write P fragments to warp-private rows of sP (no sync needed) ----
#pragma unroll
        for (int nt = 0; nt < 8; nt++) {
            uint2 p0 = make_uint2(f2tf(s[nt][0]), f2tf(s[nt][1]));
            uint2 p1 = make_uint2(f2tf(s[nt][2]), f2tf(s[nt][3]));
            *(uint2*)&sP[(w16 + g) * SP_LD + nt * 8 + 2 * t] = p0;
            *(uint2*)&sP[(w16 + 8 + g) * SP_LD + nt * 8 + 2 * t] = p1;
        }

        // ---- O += P V  (16 x 128 per warp, k = 64 keys) ----
#pragma unroll
        for (int kc = 0; kc < 8; kc++) {
            uint32_t pa[4];
            pa[0] = sP[(w16 + g) * SP_LD + kc * 8 + t];
            pa[1] = sP[(w16 + 8 + g) * SP_LD + kc * 8 + t];
            pa[2] = sP[(w16 + g) * SP_LD + kc * 8 + t + 4];
            pa[3] = sP[(w16 + 8 + g) * SP_LD + kc * 8 + t + 4];
#pragma unroll
            for (int dt = 0; dt < 16; dt++) {
                uint32_t bf[2];
                bf[0] = sV[(kc * 8 + t) * SV_LD + dt * 8 + g];
                bf[1] = sV[(kc * 8 + t + 4) * SV_LD + dt * 8 + g];
                mma_tf32(o[dt], pa, bf);
            }
        }
    }

    // ---- epilogue ----
    const float inv0 = 1.0f / l0;
    const float inv1 = 1.0f / l1;
    float* dst0 = yb + (size_t)(b * T_SZ + row0) * C_SZ + h * HD;
    float* dst1 = yb + (size_t)(b * T_SZ + row1) * C_SZ + h * HD;
#pragma unroll
    for (int dt = 0; dt < 16; dt++) {
        *(float2*)&dst0[dt * 8 + 2 * t] = make_float2(o[dt][0] * inv0, o[dt][1] * inv0);
        *(float2*)&dst1[dt * 8 + 2 * t] = make_float2(o[dt][2] * inv1, o[dt][3] * inv1);
    }
}

// ---------------- launch ---------------------------------------------------------
extern "C" void kernel_launch(void* const* d_in, const int* in_sizes, int n_in,
                              void* d_out, int out_size) {
    const float* x     = (const float*)d_in[0];
    const float* cosb  = (const float*)d_in[1];
    const float* sinb  = (const float*)d_in[2];
    const float* wq    = (const float*)d_in[3];
    const float* wk    = (const float*)d_in[4];
    const float* wv    = (const float*)d_in[5];
    const float* wproj = (const float*)d_in[6];
    float* out = (float*)d_out;

    float *qp, *kp, *vp, *yp;
    cudaGetSymbolAddress((void**)&qp, g_q);
    cudaGetSymbolAddress((void**)&kp, g_k);
    cudaGetSymbolAddress((void**)&vp, g_v);
    cudaGetSymbolAddress((void**)&yp, g_y);

    const int M = B_SZ * T_SZ;   // 4096

    // QKV projections (TF32 tensor cores)
    gemm_tf32<<<dim3((NH * HD) / 128, M / 128), 256>>>(x, wq, qp, M, NH * HD, C_SZ);
    gemm_tf32<<<dim3((NKV * HD) / 128, M / 128), 256>>>(x, wk, kp, M, NKV * HD, C_SZ);
    gemm_tf32<<<dim3((NKV * HD) / 128, M / 128), 256>>>(x, wv, vp, M, NKV * HD, C_SZ);

    // RoPE + RMSNorm on q and k
    rope_rmsnorm<<<M * NH, 128>>>(qp, cosb, sinb, NH);
    rope_rmsnorm<<<M * NKV, 128>>>(kp, cosb, sinb, NKV);

    // attention (TF32 tensor cores)
    const int smem = (BN * SK_LD + BN * SV_LD + BM * SP_LD) * sizeof(uint32_t); // ~103KB
    cudaFuncSetAttribute(attn_tc, cudaFuncAttributeMaxDynamicSharedMemorySize, smem);
    attn_tc<<<dim3(T_SZ / BM, NH, B_SZ), 256, smem>>>(qp, kp, vp, yp);

    // output projection (TF32 tensor cores)
    gemm_tf32<<<dim3(C_SZ / 128, M / 128), 256>>>(yp, wproj, out, M, C_SZ, C_SZ);
}